// round 2
// baseline (speedup 1.0000x reference)
#include <cuda_runtime.h>

typedef unsigned long long ull;

// ---------------- problem constants ----------------
#define TT    1024
#define BB    64
#define WW    512
#define W3    1536
#define LL    2

// ---------------- kernel config --------------------
#define GRID    128     // 64 CTAs per GEMM-group; all co-resident (<=148 SMs, 1 CTA/SM)
#define NTH     256
#define NGC     8       // gate-columns per CTA (64*8 = 512)
#define NCOLS   (NGC*3) // 24 actual weight columns per CTA
#define CHUNK   64      // K-chunk staged in smem
#define NCHUNK  16      // K = 1024
#define AS      68      // A smem row stride (pad 4 floats -> conflict-free, 16B-aligned)
#define WS      1028    // W smem row stride (pad 4 floats -> conflict-free, 16B-aligned)

#define SMEM_FLOATS (NCOLS*WS + 2*BB*AS + BB)
#define SMEM_BYTES  (SMEM_FLOATS * 4)

// ---------------- persistent device state ----------
__device__ float g_h0[2][BB * WW];      // double-buffered layer-0 hidden
__device__ float g_h1[2][BB * WW];      // double-buffered layer-1 hidden
__device__ unsigned g_cnt = 0;          // barrier arrival counter (self-resetting)
__device__ volatile unsigned g_gen = 0; // barrier generation (monotonic across launches)
__device__ int g_reset_mode = 0;        // 0=uint8/bool, 1=int32, 2=float32

// ---------------- reset dtype sniffing --------------
// bool/uint8 bytes: uint32 view gives combos of 0x00/0x01 bytes (max in (1, 0x01010101]).
// int32 0/1: max <= 1.  float32 0/1.0f: max = 0x3F800000.
__global__ void sniff_resets_kernel(const unsigned* __restrict__ r)
{
    __shared__ unsigned red[256];
    unsigned m = 0;
    for (int i = threadIdx.x; i < (TT * BB) / 4; i += 256)
        m = max(m, r[i]);
    red[threadIdx.x] = m;
    __syncthreads();
    for (int s = 128; s > 0; s >>= 1) {
        if (threadIdx.x < s) red[threadIdx.x] = max(red[threadIdx.x], red[threadIdx.x + s]);
        __syncthreads();
    }
    if (threadIdx.x == 0) {
        unsigned mx = red[0];
        g_reset_mode = (mx <= 1u) ? 1 : (mx >= 0x10000000u ? 2 : 0);
    }
}

__device__ __forceinline__ float reset_mask(const void* r, int mode, int idx)
{
    if (mode == 1) return ((const int*)r)[idx] != 0 ? 0.0f : 1.0f;
    if (mode == 2) return ((const float*)r)[idx] != 0.0f ? 0.0f : 1.0f;
    return ((const unsigned char*)r)[idx] != 0 ? 0.0f : 1.0f;
}

// ---------------- packed f32x2 FMA ------------------
__device__ __forceinline__ void ffma2(ull& acc, ull a, ull b)
{
    asm("fma.rn.f32x2 %0, %1, %2, %0;" : "+l"(acc) : "l"(a), "l"(b));
}
__device__ __forceinline__ float hadd2(ull v)
{
    return __uint_as_float((unsigned)v) + __uint_as_float((unsigned)(v >> 32));
}

// --------------- inner product over one K-chunk -----
// per thread: 2 batch rows x 3 gate columns, K-packed by 2 via f32x2
__device__ __forceinline__ void mma_chunk(
    const float* __restrict__ As,
    const float* __restrict__ wr, const float* __restrict__ wz, const float* __restrict__ wn,
    int kbase, int b0o, int b1o,
    ull& r0, ull& r1, ull& z0, ull& z1, ull& n0, ull& n1)
{
#pragma unroll
    for (int kk = 0; kk < CHUNK; kk += 4) {
        float4 a0 = *(const float4*)(As + b0o + kk);
        float4 a1 = *(const float4*)(As + b1o + kk);
        float4 fr = *(const float4*)(wr + kbase + kk);
        float4 fz = *(const float4*)(wz + kbase + kk);
        float4 fn = *(const float4*)(wn + kbase + kk);
        const ull* a0p = (const ull*)&a0;
        const ull* a1p = (const ull*)&a1;
        const ull* frp = (const ull*)&fr;
        const ull* fzp = (const ull*)&fz;
        const ull* fnp = (const ull*)&fn;
        ffma2(r0, a0p[0], frp[0]); ffma2(r0, a0p[1], frp[1]);
        ffma2(r1, a1p[0], frp[0]); ffma2(r1, a1p[1], frp[1]);
        ffma2(z0, a0p[0], fzp[0]); ffma2(z0, a0p[1], fzp[1]);
        ffma2(z1, a1p[0], fzp[0]); ffma2(z1, a1p[1], fzp[1]);
        ffma2(n0, a0p[0], fnp[0]); ffma2(n0, a0p[1], fnp[1]);
        ffma2(n1, a1p[0], fnp[0]); ffma2(n1, a1p[1], fnp[1]);
    }
}

__global__ void __launch_bounds__(NTH, 1)
gru_scan_kernel(const float* __restrict__ ins,
                const void* __restrict__ resets,
                const float* __restrict__ Wi, const float* __restrict__ bi,
                const float* __restrict__ Wh, const float* __restrict__ bhn,
                float* __restrict__ out)
{
    extern __shared__ float smem[];
    float* Wsm = smem;                       // [NCOLS][WS]   transposed weights
    float* Asm = smem + NCOLS * WS;          // [2][BB][AS]   double-buffered A chunk
    float* rm  = Asm  + 2 * BB * AS;         // [BB]          per-batch reset mask

    const int tid   = threadIdx.x;
    const int cta   = blockIdx.x;
    const int group = cta >> 6;              // 0: layer-1 task, 1: layer-0 task
    const int lyr   = (group == 0) ? 1 : 0;
    const int gwBase = (cta & 63) * NGC;
    const int tn = tid & 7;                  // gate-column within CTA
    const int tm = tid >> 3;                 // batch pair
    const int b0 = tm * 2, b1 = tm * 2 + 1;
    const int w  = gwBase + tn;              // global gate column [0,512)
    const int rmode = g_reset_mode;

    // ---- one-time: load this CTA's weight slice into smem, transposed [n][k] ----
    // Wcat[k][c]: k<512 -> Wi[lyr][k][c], else Wh[lyr][k-512][c]
    const float* WiL = Wi + (size_t)lyr * WW * W3;
    const float* WhL = Wh + (size_t)lyr * WW * W3;
    for (int idx = tid; idx < NCOLS * WW * 2; idx += NTH) {
        int n = idx % NCOLS;
        int k = idx / NCOLS;
        int gl = n / 3, gate = n - gl * 3;
        int c = gwBase + gl + gate * WW;
        float v = (k < WW) ? WiL[(size_t)k * W3 + c] : WhL[(size_t)(k - WW) * W3 + c];
        Wsm[n * WS + k] = v;
    }
    const float bir  = bi[lyr * W3 + w];
    const float biz  = bi[lyr * W3 + WW + w];
    const float bin  = bi[lyr * W3 + 2 * WW + w];
    const float bhnw = bhn[lyr * WW + w];

    unsigned gen = 0;
    if (tid == 0) gen = g_gen;               // per-launch barrier base (monotonic)
    __syncthreads();                         // weights + gen ready

    float* out_carry = out;                  // [L][B][W]
    float* out_ys    = out + LL * BB * WW;   // [T][B][W]

    const float* wr = &Wsm[(tn * 3 + 0) * WS];
    const float* wz = &Wsm[(tn * 3 + 1) * WS];
    const float* wn = &Wsm[(tn * 3 + 2) * WS];
    const int b0o = b0 * AS, b1o = b1 * AS;
    const int lb  = tid >> 2;                // loader: row
    const int lf0 = tid & 3;                 // loader: float4 phase

    // phase p: group1 computes layer0(t=p) for p<T; group0 computes layer1(t=p-1) for p>=1
    for (int p = 0; p <= TT; ++p) {
        const bool active = (group == 1) ? (p < TT) : (p >= 1);
        if (active) {
            const int t = (group == 1) ? p : (p - 1);
            const float* srcI = (group == 1) ? (ins + (size_t)t * BB * WW)
                                             : &g_h0[(p - 1) & 1][0];
            const float* srcH = (group == 1) ? &g_h0[(p == 0) ? 1 : ((p - 1) & 1)][0]
                                             : &g_h1[(p - 1) & 1][0];
            const bool zeroH = (group == 1) ? (p == 0) : (p == 1);

            if (tid < BB) {
                float m = 0.0f;
                if (!zeroH) m = reset_mask(resets, rmode, t * BB + tid);
                rm[tid] = m;
            }
            __syncthreads();

            ull r0 = 0, r1 = 0, z0 = 0, z1 = 0;
            ull ni0 = 0, ni1 = 0, nh0 = 0, nh1 = 0;

            // ---- stage chunk 0 (I-half, never masked) ----
            {
#pragma unroll
                for (int it = 0; it < 4; ++it) {
                    int f4 = lf0 + it * 4;
                    float4 v = __ldcg((const float4*)(srcI + (size_t)lb * WW + f4 * 4));
                    *(float4*)(Asm + lb * AS + f4 * 4) = v;
                }
            }
            __syncthreads();

            float4 pf[4]; float pm = 1.0f;
            for (int c = 0; c < NCHUNK; ++c) {
                if (c + 1 < NCHUNK) {        // prefetch next chunk into registers
                    int cn = c + 1;
                    const float* src = (cn < 8) ? srcI : srcH;
                    int kOff = (cn < 8) ? cn * CHUNK : (cn - 8) * CHUNK;
                    pm = (cn < 8) ? 1.0f : rm[lb];
#pragma unroll
                    for (int it = 0; it < 4; ++it) {
                        int f4 = lf0 + it * 4;
                        pf[it] = __ldcg((const float4*)(src + (size_t)lb * WW + kOff + f4 * 4));
                    }
                }
                const float* As = Asm + (c & 1) * BB * AS;
                if (c < 8) mma_chunk(As, wr, wz, wn, c * CHUNK, b0o, b1o, r0, r1, z0, z1, ni0, ni1);
                else       mma_chunk(As, wr, wz, wn, c * CHUNK, b0o, b1o, r0, r1, z0, z1, nh0, nh1);
                if (c + 1 < NCHUNK) {        // commit prefetch to the other buffer
                    float* dst = Asm + ((c + 1) & 1) * BB * AS;
#pragma unroll
                    for (int it = 0; it < 4; ++it) {
                        int f4 = lf0 + it * 4;
                        float4 v = pf[it];
                        *(float4*)(dst + lb * AS + f4 * 4) =
                            make_float4(v.x * pm, v.y * pm, v.z * pm, v.w * pm);
                    }
                }
                __syncthreads();
            }

            // ---- gates + state update (local: this thread owns {w, w+512, w+1024}) ----
            const float m0 = rm[b0], m1 = rm[b1];
            const float hp0 = __ldcg(srcH + b0 * WW + w) * m0;
            const float hp1 = __ldcg(srcH + b1 * WW + w) * m1;
            const float gr0 = bir + hadd2(r0), gr1 = bir + hadd2(r1);
            const float gz0 = biz + hadd2(z0), gz1 = biz + hadd2(z1);
            const float gi0 = bin + hadd2(ni0), gi1 = bin + hadd2(ni1);
            const float gh0 = hadd2(nh0), gh1 = hadd2(nh1);
            const float rr0 = 1.0f / (1.0f + expf(-gr0));
            const float rr1 = 1.0f / (1.0f + expf(-gr1));
            const float zz0 = 1.0f / (1.0f + expf(-gz0));
            const float zz1 = 1.0f / (1.0f + expf(-gz1));
            const float nn0 = tanhf(gi0 + rr0 * (gh0 + bhnw));
            const float nn1 = tanhf(gi1 + rr1 * (gh1 + bhnw));
            const float hnew0 = (1.0f - zz0) * nn0 + zz0 * hp0;
            const float hnew1 = (1.0f - zz1) * nn1 + zz1 * hp1;

            float* dst = (group == 1) ? &g_h0[p & 1][0] : &g_h1[p & 1][0];
            dst[b0 * WW + w] = hnew0;
            dst[b1 * WW + w] = hnew1;
            if (group == 0) {
                out_ys[(size_t)t * BB * WW + b0 * WW + w] = hnew0;
                out_ys[(size_t)t * BB * WW + b1 * WW + w] = hnew1;
                if (p == TT) {               // final h1 carry
                    out_carry[1 * BB * WW + b0 * WW + w] = hnew0;
                    out_carry[1 * BB * WW + b1 * WW + w] = hnew1;
                }
            } else if (p == TT - 1) {        // final h0 carry
                out_carry[b0 * WW + w] = hnew0;
                out_carry[b1 * WW + w] = hnew1;
            }
        }

        // ---- grid barrier (self-resetting counter + monotonic generation) ----
        __syncthreads();
        if (tid == 0) {
            __threadfence();
            unsigned a = atomicAdd(&g_cnt, 1);
            gen += 1;
            if (a == GRID - 1) {
                g_cnt = 0;
                __threadfence();
                g_gen = gen;
            } else {
                while (g_gen < gen) { __nanosleep(20); }
                __threadfence();
            }
        }
        __syncthreads();
    }
}

extern "C" void kernel_launch(void* const* d_in, const int* in_sizes, int n_in,
                              void* d_out, int out_size)
{
    const float* ins    = (const float*)d_in[0];
    const void*  resets = (const void*)d_in[1];
    const float* Wi     = (const float*)d_in[2];
    const float* bi     = (const float*)d_in[3];
    const float* Wh     = (const float*)d_in[4];
    const float* bhn    = (const float*)d_in[5];
    float*       out    = (float*)d_out;

    sniff_resets_kernel<<<1, 256>>>((const unsigned*)resets);

    cudaFuncSetAttribute(gru_scan_kernel,
                         cudaFuncAttributeMaxDynamicSharedMemorySize, SMEM_BYTES);
    gru_scan_kernel<<<GRID, NTH, SMEM_BYTES>>>(ins, resets, Wi, bi, Wh, bhn, out);
}